// round 1
// baseline (speedup 1.0000x reference)
#include <cuda_runtime.h>
#include <cstdint>
#include <cstddef>

#define N_USERS 50000
#define N_ITEMS 50000
#define NN      100000
#define CC      5
#define DD      64
#define AA      32
#define LLAYERS 2
#define EE      1600000
#define ALPHA   0.3f
#define RS      (CC*DD)            /* 320 floats per node record */

#define OUT_PAD_OFF 32000000       /* zero pad row (items row 50000) */
#define OUT_CRI_OFF 32000320       /* cri_mean */

#define ATTN_SMEM  ((CC*DD*AA + CC*AA + 8*RS) * (int)sizeof(float))  /* 51840 B */

// -------- scratch (device globals; no allocation allowed) --------
static __device__ __align__(256) float g_pre[(size_t)NN * RS];   // 128 MB
static __device__ __align__(256) float g_emb[(size_t)NN * RS];   // 128 MB
static __device__ float g_cri[3 * RS];
static __device__ float g_M[LLAYERS * CC * DD * DD];

__device__ __forceinline__ float leaky(float x) { return x >= 0.f ? x : ALPHA * x; }

// ---------------------------------------------------------------
// cri chain: cri1 = leaky(cri0 @ Wrel0), cri2 = leaky(cri1 @ Wrel1)
// also writes cri_mean and the items zero-pad row to d_out.
// ---------------------------------------------------------------
__global__ void prep_cri_kernel(const float* __restrict__ cri_emb,
                                const float* __restrict__ W_rel,
                                float* __restrict__ out) {
    __shared__ float c0[RS], c1[RS], c2[RS];
    int t = threadIdx.x;               // 320 threads
    int c = t >> 6, d = t & 63;
    c0[t] = cri_emb[t];
    g_cri[t] = c0[t];
    __syncthreads();
    float s = 0.f;
    #pragma unroll 8
    for (int j = 0; j < 64; j++) s += c0[c * 64 + j] * W_rel[j * 64 + d];
    c1[t] = leaky(s);
    g_cri[RS + t] = c1[t];
    __syncthreads();
    s = 0.f;
    #pragma unroll 8
    for (int j = 0; j < 64; j++) s += c1[c * 64 + j] * W_rel[4096 + j * 64 + d];
    c2[t] = leaky(s);
    g_cri[2 * RS + t] = c2[t];
    __syncthreads();
    out[OUT_CRI_OFF + t] = (c0[t] + c1[t] + c2[t]) * (1.f / 3.f);
    out[OUT_PAD_OFF + t] = 0.f;
}

// ---------------------------------------------------------------
// M[k][c] = w_gcn @ diag(cri_k[c]) @ W_gc[k]   (fused dense transform)
// one block per (k, c, p) output row; 64 threads = output col q.
// ---------------------------------------------------------------
__global__ void prep_M_kernel(const float* __restrict__ w_gcn,
                              const float* __restrict__ W_gc) {
    int b = blockIdx.x;                 // 0 .. L*C*D-1
    int k = b / (CC * DD);
    int rem = b - k * CC * DD;
    int c = rem / DD;
    int p = rem - c * DD;
    int q = threadIdx.x;
    __shared__ float scw[64];
    scw[q] = w_gcn[p * 64 + q] * g_cri[k * RS + c * 64 + q];
    __syncthreads();
    const float* Wg = W_gc + k * 4096;
    float s = 0.f;
    #pragma unroll 8
    for (int j = 0; j < 64; j++) s += scw[j] * Wg[j * 64 + q];
    g_M[((k * CC + c) * DD + p) * DD + q] = s;
}

// ---------------------------------------------------------------
// SpMM: emb[row,c,:] += val * pre[col,c,:]. 16 lanes per edge (float4 each).
// Edges ordered c-major so per-criterion working set (~51MB) is L2-resident.
// ---------------------------------------------------------------
__global__ void __launch_bounds__(256) spmm_kernel(const int* __restrict__ rows,
                                                   const int* __restrict__ cols,
                                                   const float* __restrict__ vals) {
    int g = blockIdx.x * 16 + (threadIdx.x >> 4);   // edge id over C*E (c-major)
    int lane = threadIdx.x & 15;
    if (g >= CC * EE) return;
    int c = g / EE;
    int r  = __ldg(rows + g);
    int co = __ldg(cols + g);
    float v = __ldg(vals + g);
    const float4* src = reinterpret_cast<const float4*>(g_pre + ((size_t)co * CC + c) * DD) + lane;
    float4 x = __ldg(src);
    float4* dst = reinterpret_cast<float4*>(g_emb + ((size_t)r * CC + c) * DD) + lane;
    atomicAdd(dst, make_float4(v * x.x, v * x.y, v * x.z, v * x.w));  // RED.v4.f32 (sm_90+)
}

// ---------------------------------------------------------------
// Dense transform: emb[n,c,:] = leaky(emb[n,c,:] @ M[k][c])   (in place)
// block: 64 rows x one criterion; 4 threads/row, 16 outputs each.
// ---------------------------------------------------------------
__global__ void __launch_bounds__(256) gemm_kernel(int k) {
    __shared__ float sM[DD * DD];
    __shared__ float sIn[64 * 65];
    int c = blockIdx.y;
    int n0 = blockIdx.x * 64;
    int tid = threadIdx.x;

    const float* Mg = g_M + (size_t)(k * CC + c) * DD * DD;
    for (int i = tid; i < 4096; i += 256) sM[i] = Mg[i];
    for (int i = tid; i < 4096; i += 256) {
        int r = i >> 6, j = i & 63;
        int n = n0 + r;
        sIn[r * 65 + j] = (n < NN) ? g_emb[((size_t)n * CC + c) * DD + j] : 0.f;
    }
    __syncthreads();

    int row = tid >> 2;
    int dgq = (tid & 3) * 4;           // float4 group base (outputs dgq*4 .. dgq*4+15)
    float acc[16];
    #pragma unroll
    for (int m = 0; m < 16; m++) acc[m] = 0.f;
    const float4* sM4 = reinterpret_cast<const float4*>(sM);
    for (int j = 0; j < 64; j++) {
        float a = sIn[row * 65 + j];
        #pragma unroll
        for (int m = 0; m < 4; m++) {
            float4 mv = sM4[j * 16 + dgq + m];
            acc[m * 4 + 0] += a * mv.x;
            acc[m * 4 + 1] += a * mv.y;
            acc[m * 4 + 2] += a * mv.z;
            acc[m * 4 + 3] += a * mv.w;
        }
    }
    int n = n0 + row;
    if (n < NN) {
        float* dst = g_emb + ((size_t)n * CC + c) * DD + dgq * 4;
        #pragma unroll
        for (int m = 0; m < 4; m++) {
            float4 o;
            o.x = leaky(acc[m * 4 + 0]);
            o.y = leaky(acc[m * 4 + 1]);
            o.z = leaky(acc[m * 4 + 2]);
            o.w = leaky(acc[m * 4 + 3]);
            reinterpret_cast<float4*>(dst)[m] = o;
        }
    }
}

// ---------------------------------------------------------------
// Attention: one warp per node.
//   t[i][c][a]   = sum_d emb[n,c,d] * W1[i,d,a]         (a = lane)
//   s[i][c]      = sum_a tanh(t) * W2[i,a]              (warp bfly reduce)
//   attn         = softmax_c(s)
//   pre[n,i,:]   = leaky(sum_c attn[i][c] * emb[n,c,:]) -> g_pre
//   acc(d_out)  += pre   (scaled by 1/3 on last layer)
// ---------------------------------------------------------------
__global__ void __launch_bounds__(256) attn_kernel(const float* __restrict__ W1,
                                                   const float* __restrict__ W2,
                                                   float* __restrict__ outAcc,
                                                   int last) {
    extern __shared__ float smem[];
    float* sW1 = smem;                    // C*D*A = 10240
    float* sW2 = sW1 + CC * DD * AA;      // 160
    float* sE  = sW2 + CC * AA;           // 8 * 320

    int tid = threadIdx.x;
    for (int i = tid; i < CC * DD * AA; i += 256) sW1[i] = W1[i];
    if (tid < CC * AA) sW2[tid] = W2[tid];

    int w = tid >> 5, lane = tid & 31;
    int n = blockIdx.x * 8 + w;
    float* myE = sE + w * RS;
    if (n < NN) {
        const float* src = g_emb + (size_t)n * RS;
        #pragma unroll
        for (int i = lane; i < RS; i += 32) myE[i] = src[i];
    }
    __syncthreads();
    if (n >= NN) return;

    float t[25];
    #pragma unroll
    for (int ic = 0; ic < 25; ic++) t[ic] = 0.f;

    #pragma unroll 2
    for (int d = 0; d < 64; d++) {
        float e0 = myE[d], e1 = myE[64 + d], e2 = myE[128 + d];
        float e3 = myE[192 + d], e4 = myE[256 + d];
        #pragma unroll
        for (int i = 0; i < 5; i++) {
            float wv = sW1[(i * 64 + d) * 32 + lane];
            t[i * 5 + 0] += e0 * wv;
            t[i * 5 + 1] += e1 * wv;
            t[i * 5 + 2] += e2 * wv;
            t[i * 5 + 3] += e3 * wv;
            t[i * 5 + 4] += e4 * wv;
        }
    }

    // tanh -> weight by W2[a] -> reduce over a (lanes)
    #pragma unroll
    for (int ic = 0; ic < 25; ic++) {
        float th;
        asm("tanh.approx.f32 %0, %1;" : "=f"(th) : "f"(t[ic]));
        float v = th * sW2[(ic / 5) * 32 + lane];
        v += __shfl_xor_sync(0xffffffffu, v, 16);
        v += __shfl_xor_sync(0xffffffffu, v, 8);
        v += __shfl_xor_sync(0xffffffffu, v, 4);
        v += __shfl_xor_sync(0xffffffffu, v, 2);
        v += __shfl_xor_sync(0xffffffffu, v, 1);
        t[ic] = v;     // all lanes now hold s[i][c]
    }

    // softmax over c per i (redundant across lanes)
    float at[25];
    #pragma unroll
    for (int i = 0; i < 5; i++) {
        float m = t[i * 5];
        #pragma unroll
        for (int c2 = 1; c2 < 5; c2++) m = fmaxf(m, t[i * 5 + c2]);
        float ssum = 0.f;
        #pragma unroll
        for (int c2 = 0; c2 < 5; c2++) {
            float e = __expf(t[i * 5 + c2] - m);
            at[i * 5 + c2] = e;
            ssum += e;
        }
        float r = 1.f / ssum;
        #pragma unroll
        for (int c2 = 0; c2 < 5; c2++) at[i * 5 + c2] *= r;
    }

    // output: new pre + accumulate into d_out
    size_t base = (size_t)n * RS;
    #pragma unroll
    for (int i = 0; i < 5; i++) {
        float o0 = 0.f, o1 = 0.f;
        #pragma unroll
        for (int c2 = 0; c2 < 5; c2++) {
            float a = at[i * 5 + c2];
            o0 += a * myE[c2 * 64 + lane];
            o1 += a * myE[c2 * 64 + lane + 32];
        }
        o0 = leaky(o0);
        o1 = leaky(o1);
        size_t off = base + i * 64 + lane;
        g_pre[off] = o0;
        g_pre[off + 32] = o1;
        float a0 = outAcc[off] + o0;
        float a1 = outAcc[off + 32] + o1;
        if (last) { a0 *= (1.f / 3.f); a1 *= (1.f / 3.f); }
        outAcc[off] = a0;
        outAcc[off + 32] = a1;
    }
}

// ---------------------------------------------------------------
extern "C" void kernel_launch(void* const* d_in, const int* in_sizes, int n_in,
                              void* d_out, int out_size) {
    (void)in_sizes; (void)n_in; (void)out_size;
    const int*   rows     = (const int*)  d_in[0];
    const int*   cols     = (const int*)  d_in[1];
    const float* vals     = (const float*)d_in[2];
    const float* user_emb = (const float*)d_in[3];
    const float* item_emb = (const float*)d_in[4];
    const float* cri_emb  = (const float*)d_in[5];
    const float* w_gcn    = (const float*)d_in[6];
    const float* W_gc     = (const float*)d_in[7];
    const float* W_rel    = (const float*)d_in[8];
    const float* W1       = (const float*)d_in[9];
    const float* W2       = (const float*)d_in[10];
    float* out = (float*)d_out;

    void *pre_addr = nullptr, *emb_addr = nullptr;
    cudaGetSymbolAddress(&pre_addr, g_pre);
    cudaGetSymbolAddress(&emb_addr, g_emb);
    float* pre_d = (float*)pre_addr;

    cudaFuncSetAttribute(attn_kernel, cudaFuncAttributeMaxDynamicSharedMemorySize,
                         ATTN_SMEM);

    const size_t half = (size_t)N_USERS * RS * sizeof(float);   // 64 MB
    // pre = concat(user, item); acc (in d_out) = pre
    cudaMemcpyAsync(pre_d, user_emb, half, cudaMemcpyDeviceToDevice);
    cudaMemcpyAsync(pre_d + (size_t)N_USERS * RS, item_emb, half, cudaMemcpyDeviceToDevice);
    cudaMemcpyAsync(out, user_emb, half, cudaMemcpyDeviceToDevice);
    cudaMemcpyAsync(out + (size_t)N_USERS * RS, item_emb, half, cudaMemcpyDeviceToDevice);

    prep_cri_kernel<<<1, RS>>>(cri_emb, W_rel, out);
    prep_M_kernel<<<LLAYERS * CC * DD, DD>>>(w_gcn, W_gc);

    for (int k = 0; k < LLAYERS; k++) {
        cudaMemsetAsync(emb_addr, 0, (size_t)NN * RS * sizeof(float));
        spmm_kernel<<<(CC * EE) / 16, 256>>>(rows, cols, vals);
        gemm_kernel<<<dim3((NN + 63) / 64, CC), 256>>>(k);
        attn_kernel<<<(NN + 7) / 8, 256, ATTN_SMEM>>>(W1, W2, out, k == LLAYERS - 1);
    }
}

// round 3
// speedup vs baseline: 1.6800x; 1.6800x over previous
#include <cuda_runtime.h>
#include <cuda_bf16.h>
#include <cstdint>
#include <cstddef>

#define N_USERS 50000
#define N_ITEMS 50000
#define NN      100000
#define CC      5
#define DD      64
#define AA      32
#define LLAYERS 2
#define EE      1600000
#define TOTE    (CC*EE)            /* 8,000,000 edges total */
#define NSEG    (CC*NN)            /* 500,000 CSR segments  */
#define ALPHA   0.3f
#define RS      (CC*DD)            /* 320 floats per node record */

#define OUT_PAD_OFF 32000000       /* zero pad row (items row 50000) */
#define OUT_CRI_OFF 32000320       /* cri_mean */

#define ATTN_SMEM  ((CC*DD*AA + CC*AA + 8*RS) * (int)sizeof(float))  /* 51840 B */
#define GEMM_SMEM  ((64*64 + 128*68) * (int)sizeof(float))           /* 51200 B */

// -------- scratch (device globals; no allocation allowed) --------
static __device__ __align__(256) float         g_pre[(size_t)NN * RS];    // 128 MB  (attn output, fp32)
static __device__ __align__(256) __nv_bfloat16 g_pret[(size_t)NN * RS];   //  64 MB  (pre @ M, bf16)
static __device__ __align__(256) __nv_bfloat16 g_emb[(size_t)NN * RS];    //  64 MB  (leaky(spmm), bf16)
static __device__ __align__(256) int2          g_payload[TOTE];           //  64 MB  (col, val)
static __device__ int   g_counts[NSEG];
static __device__ int   g_offs[NSEG + 1];
static __device__ int   g_cursor[NSEG];
static __device__ int   g_bsum[256];
static __device__ float g_cri[3 * RS];
static __device__ float g_M[LLAYERS * CC * DD * DD];

__device__ __forceinline__ float leaky(float x) { return x >= 0.f ? x : ALPHA * x; }

// ================= CSR build (once per launch; reused by both layers) =========
__global__ void hist_k(const int* __restrict__ rows) {
    int e = blockIdx.x * 256 + threadIdx.x;
    if (e >= TOTE) return;
    int c = e / EE;
    atomicAdd(&g_counts[c * NN + rows[e]], 1);
}

// block scans 2048 counts (256 thr x 8), writes block-local exclusive offs + block sum
__global__ void scan1_k() {
    __shared__ int wsum[8];
    int blk = blockIdx.x, t = threadIdx.x;
    int base = blk * 2048 + t * 8;
    int v[8];
    #pragma unroll
    for (int i = 0; i < 8; i++) { int idx = base + i; v[i] = (idx < NSEG) ? g_counts[idx] : 0; }
    int tsum = 0;
    #pragma unroll
    for (int i = 0; i < 8; i++) tsum += v[i];
    int lane = t & 31, w = t >> 5;
    int x = tsum;
    #pragma unroll
    for (int o = 1; o < 32; o <<= 1) { int y = __shfl_up_sync(0xffffffffu, x, o); if (lane >= o) x += y; }
    if (lane == 31) wsum[w] = x;
    __syncthreads();
    if (t == 0) {
        int run = 0;
        #pragma unroll
        for (int i = 0; i < 8; i++) { int tmp = wsum[i]; wsum[i] = run; run += tmp; }
        g_bsum[blk] = run;
    }
    __syncthreads();
    int run = wsum[w] + x - tsum;     // exclusive prefix of this thread within block
    #pragma unroll
    for (int i = 0; i < 8; i++) { int idx = base + i; if (idx < NSEG) g_offs[idx] = run; run += v[i]; }
}

__global__ void scan2_k(int nblk) {     // exclusive scan of block sums (nblk <= 256)
    __shared__ int wsum[8];
    int t = threadIdx.x;
    int v = (t < nblk) ? g_bsum[t] : 0;
    int lane = t & 31, w = t >> 5;
    int x = v;
    #pragma unroll
    for (int o = 1; o < 32; o <<= 1) { int y = __shfl_up_sync(0xffffffffu, x, o); if (lane >= o) x += y; }
    if (lane == 31) wsum[w] = x;
    __syncthreads();
    if (t == 0) {
        int run = 0;
        #pragma unroll
        for (int i = 0; i < 8; i++) { int tmp = wsum[i]; wsum[i] = run; run += tmp; }
    }
    __syncthreads();
    if (t < nblk) g_bsum[t] = x + wsum[w] - v;   // exclusive
}

__global__ void scan3_k() {             // add block offsets; init cursor; offs[NSEG]=TOTE
    int idx = blockIdx.x * 256 + threadIdx.x;
    if (idx > NSEG) return;
    if (idx == NSEG) { g_offs[NSEG] = TOTE; return; }
    int v = g_offs[idx] + g_bsum[idx >> 11];
    g_offs[idx] = v;
    g_cursor[idx] = v;
}

__global__ void scatter_k(const int* __restrict__ rows, const int* __restrict__ cols,
                          const float* __restrict__ vals) {
    int e = blockIdx.x * 256 + threadIdx.x;
    if (e >= TOTE) return;
    int c = e / EE;
    int seg = c * NN + rows[e];
    int pos = atomicAdd(&g_cursor[seg], 1);
    g_payload[pos] = make_int2(cols[e], __float_as_int(vals[e]));
}

// ================= criteria chain + fused transform matrices ==================
__global__ void prep_cri_kernel(const float* __restrict__ cri_emb,
                                const float* __restrict__ W_rel,
                                float* __restrict__ out) {
    __shared__ float c0[RS], c1[RS], c2[RS];
    int t = threadIdx.x;               // 320 threads
    int c = t >> 6, d = t & 63;
    c0[t] = cri_emb[t];
    g_cri[t] = c0[t];
    __syncthreads();
    float s = 0.f;
    #pragma unroll 8
    for (int j = 0; j < 64; j++) s += c0[c * 64 + j] * W_rel[j * 64 + d];
    c1[t] = leaky(s);
    g_cri[RS + t] = c1[t];
    __syncthreads();
    s = 0.f;
    #pragma unroll 8
    for (int j = 0; j < 64; j++) s += c1[c * 64 + j] * W_rel[4096 + j * 64 + d];
    c2[t] = leaky(s);
    g_cri[2 * RS + t] = c2[t];
    __syncthreads();
    out[OUT_CRI_OFF + t] = (c0[t] + c1[t] + c2[t]) * (1.f / 3.f);
    out[OUT_PAD_OFF + t] = 0.f;
}

// M[k][c] = w_gcn @ diag(cri_k[c]) @ W_gc[k]
__global__ void prep_M_kernel(const float* __restrict__ w_gcn,
                              const float* __restrict__ W_gc) {
    int b = blockIdx.x;                 // 0 .. L*C*D-1
    int k = b / (CC * DD);
    int rem = b - k * CC * DD;
    int c = rem / DD;
    int p = rem - c * DD;
    int q = threadIdx.x;
    __shared__ float scw[64];
    scw[q] = w_gcn[p * 64 + q] * g_cri[k * RS + c * 64 + q];
    __syncthreads();
    const float* Wg = W_gc + k * 4096;
    float s = 0.f;
    #pragma unroll 8
    for (int j = 0; j < 64; j++) s += scw[j] * Wg[j * 64 + q];
    g_M[((k * CC + c) * DD + p) * DD + q] = s;
}

// ================= dense transform: pret = pre @ M[k][c]  (fp32 -> bf16) ======
// block: 128 rows x one criterion; thread = 4 rows (stride 32) x 8 cols.
#define GPITCH 68
__global__ void __launch_bounds__(256) gemm2_k(const float* __restrict__ uE,
                                               const float* __restrict__ iE,
                                               int layer) {
    extern __shared__ float sm[];
    float* sM  = sm;              // 64*64
    float* sIn = sm + 4096;       // 128*GPITCH
    int c  = blockIdx.y;
    int n0 = blockIdx.x * 128;
    int tid = threadIdx.x;

    const float* Mg = g_M + (size_t)(layer * CC + c) * 4096;
    for (int i = tid; i < 4096; i += 256) sM[i] = Mg[i];

    for (int q = tid; q < 128 * 16; q += 256) {
        int r = q >> 4, j4 = q & 15;
        int n = n0 + r;
        float4 val = make_float4(0.f, 0.f, 0.f, 0.f);
        if (n < NN) {
            const float* src;
            if (layer == 0)
                src = (n < N_USERS) ? (uE + (size_t)n * RS) : (iE + (size_t)(n - N_USERS) * RS);
            else
                src = g_pre + (size_t)n * RS;
            val = *(const float4*)(src + c * 64 + j4 * 4);
        }
        *(float4*)(sIn + r * GPITCH + j4 * 4) = val;
    }
    __syncthreads();

    int tx = tid & 7;            // col group: cols tx*8 .. +7
    int ty = tid >> 3;           // 0..31: rows ty + 32*r
    float acc[4][8];
    #pragma unroll
    for (int r = 0; r < 4; r++)
        #pragma unroll
        for (int q = 0; q < 8; q++) acc[r][q] = 0.f;

    const float* in0 = sIn + ty * GPITCH;
    for (int j = 0; j < 64; j += 4) {
        float4 a[4];
        #pragma unroll
        for (int r = 0; r < 4; r++) a[r] = *(const float4*)(in0 + (r * 32) * GPITCH + j);
        #pragma unroll
        for (int jj = 0; jj < 4; jj++) {
            float4 m0 = *(const float4*)(sM + (j + jj) * 64 + tx * 8);
            float4 m1 = *(const float4*)(sM + (j + jj) * 64 + tx * 8 + 4);
            #pragma unroll
            for (int r = 0; r < 4; r++) {
                float av = ((const float*)&a[r])[jj];
                acc[r][0] += av * m0.x; acc[r][1] += av * m0.y;
                acc[r][2] += av * m0.z; acc[r][3] += av * m0.w;
                acc[r][4] += av * m1.x; acc[r][5] += av * m1.y;
                acc[r][6] += av * m1.z; acc[r][7] += av * m1.w;
            }
        }
    }

    #pragma unroll
    for (int r = 0; r < 4; r++) {
        int n = n0 + ty + r * 32;
        if (n < NN) {
            __nv_bfloat162 b0 = __floats2bfloat162_rn(acc[r][0], acc[r][1]);
            __nv_bfloat162 b1 = __floats2bfloat162_rn(acc[r][2], acc[r][3]);
            __nv_bfloat162 b2 = __floats2bfloat162_rn(acc[r][4], acc[r][5]);
            __nv_bfloat162 b3 = __floats2bfloat162_rn(acc[r][6], acc[r][7]);
            uint4 pack;
            pack.x = *(unsigned*)&b0; pack.y = *(unsigned*)&b1;
            pack.z = *(unsigned*)&b2; pack.w = *(unsigned*)&b3;
            *(uint4*)(g_pret + ((size_t)n * CC + c) * 64 + tx * 8) = pack;
        }
    }
}

// ================= gather SpMM: emb = leaky(S @ pret)  (bf16 -> bf16) =========
// one warp per (c, node) segment; lane owns dims {2*lane, 2*lane+1}.
__global__ void __launch_bounds__(256) gather_k() {
    int gw = (blockIdx.x * 256 + threadIdx.x) >> 5;   // segment = c*NN + n
    int lane = threadIdx.x & 31;
    if (gw >= NSEG) return;
    int c = gw / NN;
    int n = gw - c * NN;
    int start = g_offs[gw], end = g_offs[gw + 1];
    const __nv_bfloat162* P = (const __nv_bfloat162*)g_pret;
    float2 a0 = make_float2(0.f, 0.f), a1 = make_float2(0.f, 0.f);
    for (int b = start; b < end; b += 32) {
        int m = end - b; if (m > 32) m = 32;
        int2 p = make_int2(0, 0);
        if (lane < m) p = g_payload[b + lane];
        int i = 0;
        for (; i + 2 <= m; i += 2) {
            int   col0 = __shfl_sync(0xffffffffu, p.x, i);
            float v0   = __int_as_float(__shfl_sync(0xffffffffu, p.y, i));
            int   col1 = __shfl_sync(0xffffffffu, p.x, i + 1);
            float v1   = __int_as_float(__shfl_sync(0xffffffffu, p.y, i + 1));
            __nv_bfloat162 x0 = __ldg(P + ((size_t)col0 * CC + c) * 32 + lane);
            __nv_bfloat162 x1 = __ldg(P + ((size_t)col1 * CC + c) * 32 + lane);
            float2 f0 = __bfloat1622float2(x0);
            float2 f1 = __bfloat1622float2(x1);
            a0.x += v0 * f0.x; a0.y += v0 * f0.y;
            a1.x += v1 * f1.x; a1.y += v1 * f1.y;
        }
        if (i < m) {
            int   col = __shfl_sync(0xffffffffu, p.x, i);
            float v   = __int_as_float(__shfl_sync(0xffffffffu, p.y, i));
            float2 f = __bfloat1622float2(__ldg(P + ((size_t)col * CC + c) * 32 + lane));
            a0.x += v * f.x; a0.y += v * f.y;
        }
    }
    float ox = leaky(a0.x + a1.x), oy = leaky(a0.y + a1.y);
    ((__nv_bfloat162*)g_emb)[((size_t)n * CC + c) * 32 + lane] = __floats2bfloat162_rn(ox, oy);
}

// ================= attention (one warp per node) ==============================
__global__ void __launch_bounds__(256) attn_kernel(const float* __restrict__ W1,
                                                   const float* __restrict__ W2,
                                                   float* __restrict__ outAcc,
                                                   int last) {
    extern __shared__ float smem[];
    float* sW1 = smem;                    // C*D*A = 10240
    float* sW2 = sW1 + CC * DD * AA;      // 160
    float* sE  = sW2 + CC * AA;           // 8 * 320

    int tid = threadIdx.x;
    for (int i = tid; i < CC * DD * AA; i += 256) sW1[i] = W1[i];
    if (tid < CC * AA) sW2[tid] = W2[tid];

    int w = tid >> 5, lane = tid & 31;
    int n = blockIdx.x * 8 + w;
    float* myE = sE + w * RS;
    if (n < NN) {
        const __nv_bfloat162* src = (const __nv_bfloat162*)g_emb + (size_t)n * (RS / 2);
        #pragma unroll
        for (int i = lane; i < RS / 2; i += 32) {
            float2 f = __bfloat1622float2(src[i]);
            *(float2*)(myE + 2 * i) = f;
        }
    }
    __syncthreads();
    if (n >= NN) return;

    float t[25];
    #pragma unroll
    for (int ic = 0; ic < 25; ic++) t[ic] = 0.f;

    #pragma unroll 2
    for (int d = 0; d < 64; d++) {
        float e0 = myE[d], e1 = myE[64 + d], e2 = myE[128 + d];
        float e3 = myE[192 + d], e4 = myE[256 + d];
        #pragma unroll
        for (int i = 0; i < 5; i++) {
            float wv = sW1[(i * 64 + d) * 32 + lane];
            t[i * 5 + 0] += e0 * wv;
            t[i * 5 + 1] += e1 * wv;
            t[i * 5 + 2] += e2 * wv;
            t[i * 5 + 3] += e3 * wv;
            t[i * 5 + 4] += e4 * wv;
        }
    }

    #pragma unroll
    for (int ic = 0; ic < 25; ic++) {
        float th;
        asm("tanh.approx.f32 %0, %1;" : "=f"(th) : "f"(t[ic]));
        float v = th * sW2[(ic / 5) * 32 + lane];
        v += __shfl_xor_sync(0xffffffffu, v, 16);
        v += __shfl_xor_sync(0xffffffffu, v, 8);
        v += __shfl_xor_sync(0xffffffffu, v, 4);
        v += __shfl_xor_sync(0xffffffffu, v, 2);
        v += __shfl_xor_sync(0xffffffffu, v, 1);
        t[ic] = v;
    }

    float at[25];
    #pragma unroll
    for (int i = 0; i < 5; i++) {
        float m = t[i * 5];
        #pragma unroll
        for (int c2 = 1; c2 < 5; c2++) m = fmaxf(m, t[i * 5 + c2]);
        float ssum = 0.f;
        #pragma unroll
        for (int c2 = 0; c2 < 5; c2++) {
            float e = __expf(t[i * 5 + c2] - m);
            at[i * 5 + c2] = e;
            ssum += e;
        }
        float r = 1.f / ssum;
        #pragma unroll
        for (int c2 = 0; c2 < 5; c2++) at[i * 5 + c2] *= r;
    }

    size_t base = (size_t)n * RS;
    #pragma unroll
    for (int i = 0; i < 5; i++) {
        float o0 = 0.f, o1 = 0.f;
        #pragma unroll
        for (int c2 = 0; c2 < 5; c2++) {
            float a = at[i * 5 + c2];
            o0 += a * myE[c2 * 64 + lane];
            o1 += a * myE[c2 * 64 + lane + 32];
        }
        o0 = leaky(o0);
        o1 = leaky(o1);
        size_t off = base + i * 64 + lane;
        g_pre[off] = o0;
        g_pre[off + 32] = o1;
        float a0 = outAcc[off] + o0;
        float a1 = outAcc[off + 32] + o1;
        if (last) { a0 *= (1.f / 3.f); a1 *= (1.f / 3.f); }
        outAcc[off] = a0;
        outAcc[off + 32] = a1;
    }
}

// ===============================================================================
extern "C" void kernel_launch(void* const* d_in, const int* in_sizes, int n_in,
                              void* d_out, int out_size) {
    (void)in_sizes; (void)n_in; (void)out_size;
    const int*   rows     = (const int*)  d_in[0];
    const int*   cols     = (const int*)  d_in[1];
    const float* vals     = (const float*)d_in[2];
    const float* user_emb = (const float*)d_in[3];
    const float* item_emb = (const float*)d_in[4];
    const float* cri_emb  = (const float*)d_in[5];
    const float* w_gcn    = (const float*)d_in[6];
    const float* W_gc     = (const float*)d_in[7];
    const float* W_rel    = (const float*)d_in[8];
    const float* W1       = (const float*)d_in[9];
    const float* W2       = (const float*)d_in[10];
    float* out = (float*)d_out;

    void* counts_addr = nullptr;
    cudaGetSymbolAddress(&counts_addr, g_counts);

    cudaFuncSetAttribute(attn_kernel, cudaFuncAttributeMaxDynamicSharedMemorySize, ATTN_SMEM);
    cudaFuncSetAttribute(gemm2_k,     cudaFuncAttributeMaxDynamicSharedMemorySize, GEMM_SMEM);

    // ---- CSR build (reused by both layers) ----
    const int NBLK = (NSEG + 2047) / 2048;   // 245
    cudaMemsetAsync(counts_addr, 0, NSEG * sizeof(int));
    hist_k<<<TOTE / 256, 256>>>(rows);
    scan1_k<<<NBLK, 256>>>();
    scan2_k<<<1, 256>>>(NBLK);
    scan3_k<<<(NSEG + 256) / 256, 256>>>();
    scatter_k<<<TOTE / 256, 256>>>(rows, cols, vals);

    // ---- small prep + output init ----
    prep_cri_kernel<<<1, RS>>>(cri_emb, W_rel, out);
    prep_M_kernel<<<LLAYERS * CC * DD, DD>>>(w_gcn, W_gc);

    const size_t half = (size_t)N_USERS * RS * sizeof(float);   // 64 MB
    cudaMemcpyAsync(out, user_emb, half, cudaMemcpyDeviceToDevice);
    cudaMemcpyAsync(out + (size_t)N_USERS * RS, item_emb, half, cudaMemcpyDeviceToDevice);

    // ---- layers ----
    for (int k = 0; k < LLAYERS; k++) {
        gemm2_k<<<dim3((NN + 127) / 128, CC), 256, GEMM_SMEM>>>(user_emb, item_emb, k);
        gather_k<<<NSEG / 8, 256>>>();
        attn_kernel<<<(NN + 7) / 8, 256, ATTN_SMEM>>>(W1, W2, out, k == LLAYERS - 1);
    }
}

// round 5
// speedup vs baseline: 1.6902x; 1.0061x over previous
#include <cuda_runtime.h>
#include <cuda_bf16.h>
#include <cstdint>
#include <cstddef>

#define N_USERS 50000
#define N_ITEMS 50000
#define NN      100000
#define CC      5
#define DD      64
#define AA      32
#define LLAYERS 2
#define EE      1600000
#define TOTE    (CC*EE)            /* 8,000,000 edges total */
#define NSEG    (CC*NN)            /* 500,000 CSR segments  */
#define ALPHA   0.3f
#define RS      (CC*DD)            /* 320 floats per node record */

#define OUT_PAD_OFF 32000000       /* zero pad row (items row 50000) */
#define OUT_CRI_OFF 32000320       /* cri_mean */

#define ATTN_SMEM  ((CC*DD*AA + CC*AA + 8*RS) * (int)sizeof(float))  /* 51840 B */
#define GEMM_SMEM  ((64*64 + 128*68) * (int)sizeof(float))           /* 51200 B */

// -------- scratch (device globals; no allocation allowed) --------
static __device__ __align__(256) float         g_pre[(size_t)NN * RS];    // 128 MB  (attn output, fp32)
static __device__ __align__(256) __nv_bfloat16 g_pret[(size_t)NN * RS];   //  64 MB  (pre @ M, bf16)
static __device__ __align__(256) __nv_bfloat16 g_emb[(size_t)NN * RS];    //  64 MB  (leaky(spmm), bf16)
static __device__ __align__(256) int2          g_payload[TOTE];           //  64 MB  (col, val)
static __device__ int   g_counts[NSEG];
static __device__ int   g_offs[NSEG + 1];
static __device__ int   g_cursor[NSEG];
static __device__ int   g_bsum[256];
static __device__ float g_cri[3 * RS];
static __device__ float g_M[LLAYERS * CC * DD * DD];

__device__ __forceinline__ float leaky(float x) { return x >= 0.f ? x : ALPHA * x; }

// ================= CSR build (once per launch; reused by both layers) =========
__global__ void hist_k(const int* __restrict__ rows) {
    int e = blockIdx.x * 256 + threadIdx.x;
    if (e >= TOTE) return;
    int c = e / EE;
    atomicAdd(&g_counts[c * NN + rows[e]], 1);
}

// block scans 2048 counts (256 thr x 8), writes block-local exclusive offs + block sum
__global__ void scan1_k() {
    __shared__ int wsum[8];
    int blk = blockIdx.x, t = threadIdx.x;
    int base = blk * 2048 + t * 8;
    int v[8];
    #pragma unroll
    for (int i = 0; i < 8; i++) { int idx = base + i; v[i] = (idx < NSEG) ? g_counts[idx] : 0; }
    int tsum = 0;
    #pragma unroll
    for (int i = 0; i < 8; i++) tsum += v[i];
    int lane = t & 31, w = t >> 5;
    int x = tsum;
    #pragma unroll
    for (int o = 1; o < 32; o <<= 1) { int y = __shfl_up_sync(0xffffffffu, x, o); if (lane >= o) x += y; }
    if (lane == 31) wsum[w] = x;
    __syncthreads();
    if (t == 0) {
        int run = 0;
        #pragma unroll
        for (int i = 0; i < 8; i++) { int tmp = wsum[i]; wsum[i] = run; run += tmp; }
        g_bsum[blk] = run;
    }
    __syncthreads();
    int run = wsum[w] + x - tsum;     // exclusive prefix of this thread within block
    #pragma unroll
    for (int i = 0; i < 8; i++) { int idx = base + i; if (idx < NSEG) g_offs[idx] = run; run += v[i]; }
}

__global__ void scan2_k(int nblk) {     // exclusive scan of block sums (nblk <= 256)
    __shared__ int wsum[8];
    int t = threadIdx.x;
    int v = (t < nblk) ? g_bsum[t] : 0;
    int lane = t & 31, w = t >> 5;
    int x = v;
    #pragma unroll
    for (int o = 1; o < 32; o <<= 1) { int y = __shfl_up_sync(0xffffffffu, x, o); if (lane >= o) x += y; }
    if (lane == 31) wsum[w] = x;
    __syncthreads();
    if (t == 0) {
        int run = 0;
        #pragma unroll
        for (int i = 0; i < 8; i++) { int tmp = wsum[i]; wsum[i] = run; run += tmp; }
    }
    __syncthreads();
    if (t < nblk) g_bsum[t] = x + wsum[w] - v;   // exclusive
}

__global__ void scan3_k() {             // add block offsets; init cursor; offs[NSEG]=TOTE
    int idx = blockIdx.x * 256 + threadIdx.x;
    if (idx > NSEG) return;
    if (idx == NSEG) { g_offs[NSEG] = TOTE; return; }
    int v = g_offs[idx] + g_bsum[idx >> 11];
    g_offs[idx] = v;
    g_cursor[idx] = v;
}

__global__ void scatter_k(const int* __restrict__ rows, const int* __restrict__ cols,
                          const float* __restrict__ vals) {
    int e = blockIdx.x * 256 + threadIdx.x;
    if (e >= TOTE) return;
    int c = e / EE;
    int seg = c * NN + rows[e];
    int pos = atomicAdd(&g_cursor[seg], 1);
    g_payload[pos] = make_int2(cols[e], __float_as_int(vals[e]));
}

// ================= criteria chain + fused transform matrices ==================
__global__ void prep_cri_kernel(const float* __restrict__ cri_emb,
                                const float* __restrict__ W_rel,
                                float* __restrict__ out) {
    __shared__ float c0[RS], c1[RS], c2[RS];
    int t = threadIdx.x;               // 320 threads
    int c = t >> 6, d = t & 63;
    c0[t] = cri_emb[t];
    g_cri[t] = c0[t];
    __syncthreads();
    float s = 0.f;
    #pragma unroll 8
    for (int j = 0; j < 64; j++) s += c0[c * 64 + j] * W_rel[j * 64 + d];
    c1[t] = leaky(s);
    g_cri[RS + t] = c1[t];
    __syncthreads();
    s = 0.f;
    #pragma unroll 8
    for (int j = 0; j < 64; j++) s += c1[c * 64 + j] * W_rel[4096 + j * 64 + d];
    c2[t] = leaky(s);
    g_cri[2 * RS + t] = c2[t];
    __syncthreads();
    out[OUT_CRI_OFF + t] = (c0[t] + c1[t] + c2[t]) * (1.f / 3.f);
    out[OUT_PAD_OFF + t] = 0.f;
}

// M[k][c] = w_gcn @ diag(cri_k[c]) @ W_gc[k]
__global__ void prep_M_kernel(const float* __restrict__ w_gcn,
                              const float* __restrict__ W_gc) {
    int b = blockIdx.x;                 // 0 .. L*C*D-1
    int k = b / (CC * DD);
    int rem = b - k * CC * DD;
    int c = rem / DD;
    int p = rem - c * DD;
    int q = threadIdx.x;
    __shared__ float scw[64];
    scw[q] = w_gcn[p * 64 + q] * g_cri[k * RS + c * 64 + q];
    __syncthreads();
    const float* Wg = W_gc + k * 4096;
    float s = 0.f;
    #pragma unroll 8
    for (int j = 0; j < 64; j++) s += scw[j] * Wg[j * 64 + q];
    g_M[((k * CC + c) * DD + p) * DD + q] = s;
}

// ================= dense transform: pret = pre @ M[k][c]  (fp32 -> bf16) ======
// block: 128 rows x one criterion; thread = 4 rows (stride 32) x 8 cols.
#define GPITCH 68
__global__ void __launch_bounds__(256) gemm2_k(const float* __restrict__ uE,
                                               const float* __restrict__ iE,
                                               int layer) {
    extern __shared__ float sm[];
    float* sM  = sm;              // 64*64
    float* sIn = sm + 4096;       // 128*GPITCH
    int c  = blockIdx.y;
    int n0 = blockIdx.x * 128;
    int tid = threadIdx.x;

    const float* Mg = g_M + (size_t)(layer * CC + c) * 4096;
    for (int i = tid; i < 4096; i += 256) sM[i] = Mg[i];

    for (int q = tid; q < 128 * 16; q += 256) {
        int r = q >> 4, j4 = q & 15;
        int n = n0 + r;
        float4 val = make_float4(0.f, 0.f, 0.f, 0.f);
        if (n < NN) {
            const float* src;
            if (layer == 0)
                src = (n < N_USERS) ? (uE + (size_t)n * RS) : (iE + (size_t)(n - N_USERS) * RS);
            else
                src = g_pre + (size_t)n * RS;
            val = *(const float4*)(src + c * 64 + j4 * 4);
        }
        *(float4*)(sIn + r * GPITCH + j4 * 4) = val;
    }
    __syncthreads();

    int tx = tid & 7;            // col group: cols tx*8 .. +7
    int ty = tid >> 3;           // 0..31: rows ty + 32*r
    float acc[4][8];
    #pragma unroll
    for (int r = 0; r < 4; r++)
        #pragma unroll
        for (int q = 0; q < 8; q++) acc[r][q] = 0.f;

    const float* in0 = sIn + ty * GPITCH;
    for (int j = 0; j < 64; j += 4) {
        float4 a[4];
        #pragma unroll
        for (int r = 0; r < 4; r++) a[r] = *(const float4*)(in0 + (r * 32) * GPITCH + j);
        #pragma unroll
        for (int jj = 0; jj < 4; jj++) {
            float4 m0 = *(const float4*)(sM + (j + jj) * 64 + tx * 8);
            float4 m1 = *(const float4*)(sM + (j + jj) * 64 + tx * 8 + 4);
            #pragma unroll
            for (int r = 0; r < 4; r++) {
                float av = ((const float*)&a[r])[jj];
                acc[r][0] += av * m0.x; acc[r][1] += av * m0.y;
                acc[r][2] += av * m0.z; acc[r][3] += av * m0.w;
                acc[r][4] += av * m1.x; acc[r][5] += av * m1.y;
                acc[r][6] += av * m1.z; acc[r][7] += av * m1.w;
            }
        }
    }

    #pragma unroll
    for (int r = 0; r < 4; r++) {
        int n = n0 + ty + r * 32;
        if (n < NN) {
            __nv_bfloat162 b0 = __floats2bfloat162_rn(acc[r][0], acc[r][1]);
            __nv_bfloat162 b1 = __floats2bfloat162_rn(acc[r][2], acc[r][3]);
            __nv_bfloat162 b2 = __floats2bfloat162_rn(acc[r][4], acc[r][5]);
            __nv_bfloat162 b3 = __floats2bfloat162_rn(acc[r][6], acc[r][7]);
            uint4 pack;
            pack.x = *(unsigned*)&b0; pack.y = *(unsigned*)&b1;
            pack.z = *(unsigned*)&b2; pack.w = *(unsigned*)&b3;
            *(uint4*)(g_pret + ((size_t)n * CC + c) * 64 + tx * 8) = pack;
        }
    }
}

// ================= gather SpMM: emb = leaky(S @ pret)  (bf16 -> bf16) =========
// one warp per (c, node) segment; lane owns dims {2*lane, 2*lane+1}.
__global__ void __launch_bounds__(256) gather_k() {
    int gw = (blockIdx.x * 256 + threadIdx.x) >> 5;   // segment = c*NN + n
    int lane = threadIdx.x & 31;
    if (gw >= NSEG) return;
    int c = gw / NN;
    int n = gw - c * NN;
    int start = g_offs[gw], end = g_offs[gw + 1];
    const __nv_bfloat162* P = (const __nv_bfloat162*)g_pret;
    float2 a0 = make_float2(0.f, 0.f), a1 = make_float2(0.f, 0.f);
    for (int b = start; b < end; b += 32) {
        int m = end - b; if (m > 32) m = 32;
        int2 p = make_int2(0, 0);
        if (lane < m) p = g_payload[b + lane];
        int i = 0;
        for (; i + 2 <= m; i += 2) {
            int   col0 = __shfl_sync(0xffffffffu, p.x, i);
            float v0   = __int_as_float(__shfl_sync(0xffffffffu, p.y, i));
            int   col1 = __shfl_sync(0xffffffffu, p.x, i + 1);
            float v1   = __int_as_float(__shfl_sync(0xffffffffu, p.y, i + 1));
            __nv_bfloat162 x0 = __ldg(P + ((size_t)col0 * CC + c) * 32 + lane);
            __nv_bfloat162 x1 = __ldg(P + ((size_t)col1 * CC + c) * 32 + lane);
            float2 f0 = __bfloat1622float2(x0);
            float2 f1 = __bfloat1622float2(x1);
            a0.x += v0 * f0.x; a0.y += v0 * f0.y;
            a1.x += v1 * f1.x; a1.y += v1 * f1.y;
        }
        if (i < m) {
            int   col = __shfl_sync(0xffffffffu, p.x, i);
            float v   = __int_as_float(__shfl_sync(0xffffffffu, p.y, i));
            float2 f = __bfloat1622float2(__ldg(P + ((size_t)col * CC + c) * 32 + lane));
            a0.x += v * f.x; a0.y += v * f.y;
        }
    }
    float ox = leaky(a0.x + a1.x), oy = leaky(a0.y + a1.y);
    ((__nv_bfloat162*)g_emb)[((size_t)n * CC + c) * 32 + lane] = __floats2bfloat162_rn(ox, oy);
}

// ================= attention (one warp per node) ==============================
__global__ void __launch_bounds__(256) attn_kernel(const float* __restrict__ W1,
                                                   const float* __restrict__ W2,
                                                   float* __restrict__ outAcc,
                                                   int last) {
    extern __shared__ float smem[];
    float* sW1 = smem;                    // C*D*A = 10240
    float* sW2 = sW1 + CC * DD * AA;      // 160
    float* sE  = sW2 + CC * AA;           // 8 * 320

    int tid = threadIdx.x;
    for (int i = tid; i < CC * DD * AA; i += 256) sW1[i] = W1[i];
    if (tid < CC * AA) sW2[tid] = W2[tid];

    int w = tid >> 5, lane = tid & 31;
    int n = blockIdx.x * 8 + w;
    float* myE = sE + w * RS;
    if (n < NN) {
        const __nv_bfloat162* src = (const __nv_bfloat162*)g_emb + (size_t)n * (RS / 2);
        #pragma unroll
        for (int i = lane; i < RS / 2; i += 32) {
            float2 f = __bfloat1622float2(src[i]);
            *(float2*)(myE + 2 * i) = f;
        }
    }
    __syncthreads();
    if (n >= NN) return;

    float t[25];
    #pragma unroll
    for (int ic = 0; ic < 25; ic++) t[ic] = 0.f;

    #pragma unroll 2
    for (int d = 0; d < 64; d++) {
        float e0 = myE[d], e1 = myE[64 + d], e2 = myE[128 + d];
        float e3 = myE[192 + d], e4 = myE[256 + d];
        #pragma unroll
        for (int i = 0; i < 5; i++) {
            float wv = sW1[(i * 64 + d) * 32 + lane];
            t[i * 5 + 0] += e0 * wv;
            t[i * 5 + 1] += e1 * wv;
            t[i * 5 + 2] += e2 * wv;
            t[i * 5 + 3] += e3 * wv;
            t[i * 5 + 4] += e4 * wv;
        }
    }

    #pragma unroll
    for (int ic = 0; ic < 25; ic++) {
        float th;
        asm("tanh.approx.f32 %0, %1;" : "=f"(th) : "f"(t[ic]));
        float v = th * sW2[(ic / 5) * 32 + lane];
        v += __shfl_xor_sync(0xffffffffu, v, 16);
        v += __shfl_xor_sync(0xffffffffu, v, 8);
        v += __shfl_xor_sync(0xffffffffu, v, 4);
        v += __shfl_xor_sync(0xffffffffu, v, 2);
        v += __shfl_xor_sync(0xffffffffu, v, 1);
        t[ic] = v;
    }

    float at[25];
    #pragma unroll
    for (int i = 0; i < 5; i++) {
        float m = t[i * 5];
        #pragma unroll
        for (int c2 = 1; c2 < 5; c2++) m = fmaxf(m, t[i * 5 + c2]);
        float ssum = 0.f;
        #pragma unroll
        for (int c2 = 0; c2 < 5; c2++) {
            float e = __expf(t[i * 5 + c2] - m);
            at[i * 5 + c2] = e;
            ssum += e;
        }
        float r = 1.f / ssum;
        #pragma unroll
        for (int c2 = 0; c2 < 5; c2++) at[i * 5 + c2] *= r;
    }

    size_t base = (size_t)n * RS;
    #pragma unroll
    for (int i = 0; i < 5; i++) {
        float o0 = 0.f, o1 = 0.f;
        #pragma unroll
        for (int c2 = 0; c2 < 5; c2++) {
            float a = at[i * 5 + c2];
            o0 += a * myE[c2 * 64 + lane];
            o1 += a * myE[c2 * 64 + lane + 32];
        }
        o0 = leaky(o0);
        o1 = leaky(o1);
        size_t off = base + i * 64 + lane;
        g_pre[off] = o0;
        g_pre[off + 32] = o1;
        float a0 = outAcc[off] + o0;
        float a1 = outAcc[off + 32] + o1;
        if (last) { a0 *= (1.f / 3.f); a1 *= (1.f / 3.f); }
        outAcc[off] = a0;
        outAcc[off + 32] = a1;
    }
}

// ===============================================================================
extern "C" void kernel_launch(void* const* d_in, const int* in_sizes, int n_in,
                              void* d_out, int out_size) {
    (void)in_sizes; (void)n_in; (void)out_size;
    const int*   rows     = (const int*)  d_in[0];
    const int*   cols     = (const int*)  d_in[1];
    const float* vals     = (const float*)d_in[2];
    const float* user_emb = (const float*)d_in[3];
    const float* item_emb = (const float*)d_in[4];
    const float* cri_emb  = (const float*)d_in[5];
    const float* w_gcn    = (const float*)d_in[6];
    const float* W_gc     = (const float*)d_in[7];
    const float* W_rel    = (const float*)d_in[8];
    const float* W1       = (const float*)d_in[9];
    const float* W2       = (const float*)d_in[10];
    float* out = (float*)d_out;

    void* counts_addr = nullptr;
    cudaGetSymbolAddress(&counts_addr, g_counts);

    cudaFuncSetAttribute(attn_kernel, cudaFuncAttributeMaxDynamicSharedMemorySize, ATTN_SMEM);
    cudaFuncSetAttribute(gemm2_k,     cudaFuncAttributeMaxDynamicSharedMemorySize, GEMM_SMEM);

    // ---- CSR build (reused by both layers) ----
    const int NBLK = (NSEG + 2047) / 2048;   // 245
    cudaMemsetAsync(counts_addr, 0, NSEG * sizeof(int));
    hist_k<<<TOTE / 256, 256>>>(rows);
    scan1_k<<<NBLK, 256>>>();
    scan2_k<<<1, 256>>>(NBLK);
    scan3_k<<<(NSEG + 256) / 256, 256>>>();
    scatter_k<<<TOTE / 256, 256>>>(rows, cols, vals);

    // ---- small prep + output init ----
    prep_cri_kernel<<<1, RS>>>(cri_emb, W_rel, out);
    prep_M_kernel<<<LLAYERS * CC * DD, DD>>>(w_gcn, W_gc);

    const size_t half = (size_t)N_USERS * RS * sizeof(float);   // 64 MB
    cudaMemcpyAsync(out, user_emb, half, cudaMemcpyDeviceToDevice);
    cudaMemcpyAsync(out + (size_t)N_USERS * RS, item_emb, half, cudaMemcpyDeviceToDevice);

    // ---- layers ----
    for (int k = 0; k < LLAYERS; k++) {
        gemm2_k<<<dim3((NN + 127) / 128, CC), 256, GEMM_SMEM>>>(user_emb, item_emb, k);
        gather_k<<<NSEG / 8, 256>>>();
        attn_kernel<<<(NN + 7) / 8, 256, ATTN_SMEM>>>(W1, W2, out, k == LLAYERS - 1);
    }
}